// round 8
// baseline (speedup 1.0000x reference)
#include <cuda_runtime.h>
#include <cuda_fp16.h>

#define NN 100000
#define EE 1600000
#define GG 64
#define NB 391            // ceil(NN/256) scan chunks
#define GRID 592          // 148 SMs x 4 blocks — all co-resident
#define BLK 256
#define NWARP (GRID * 8)
#define GSTRIDE (GRID * BLK)

// ---------------- device scratch ----------------
__device__ alignas(16) __half2 g_hp0[NN * 4];    // 8 feats
__device__ alignas(16) __half2 g_hp1[NN * 8];    // 16 feats
__device__ alignas(16) __half2 g_hp2[NN * 16];   // 32 feats
__device__ float4 g_z[NN];
__device__ int   g_csr[EE];
__device__ int   g_rowptr[NN];
__device__ int   g_cnt[NN];
__device__ int   g_deg[NN];
__device__ float g_dinv[NN];
__device__ float2 g_db[NN];         // {dinv, bitcast(batch)}
__device__ int   g_bsum[NB];
__device__ float g_psum[GG * 4];
__device__ int   g_pcnt[GG];
__device__ float g_Wf[64 * 4];
__device__ float g_bf[4];
__device__ unsigned g_barcnt = 0;
__device__ unsigned g_bargen = 0;

__device__ __forceinline__ unsigned h2u(__half2 h) {
    return *reinterpret_cast<unsigned*>(&h);
}

// sense-reversing grid barrier (all GRID blocks co-resident by construction)
__device__ __forceinline__ void gsync() {
    __syncthreads();
    if (threadIdx.x == 0) {
        unsigned gen = atomicAdd(&g_bargen, 0u);
        __threadfence();
        unsigned arr = atomicAdd(&g_barcnt, 1u) + 1u;
        if (arr == (unsigned)gridDim.x) {
            g_barcnt = 0u;
            __threadfence();
            atomicAdd(&g_bargen, 1u);
        } else {
            while (atomicAdd(&g_bargen, 0u) == gen) { __nanosleep(32); }
        }
    }
    __syncthreads();
}

// ---------------- fused layer phase ----------------
template<int FIN, int FOUT, bool ZOUT>
__device__ __forceinline__ void layer_phase(
    const __half2* __restrict__ hp, __half2* __restrict__ hpo,
    const float* __restrict__ W, const float* __restrict__ bias,
    const float* __restrict__ aP,
    float* sWs, float* sbs, float* sWfs)
{
    for (int i = threadIdx.x; i < FIN * FOUT; i += BLK) sWs[i] = __ldg(&W[i]);
    for (int i = threadIdx.x; i < FOUT; i += BLK) sbs[i] = __ldg(&bias[i]);
    if (ZOUT)
        for (int i = threadIdx.x; i < 256; i += BLK) sWfs[i] = g_Wf[i];
    __syncthreads();
    float a = __ldg(aP);

    constexpr int L = FIN / 2;
    constexpr int NPW = 32 / L;
    constexpr int UNITS = NN / NPW;    // NN divisible by 8/4/2 exactly
    int gw = blockIdx.x * 8 + (threadIdx.x >> 5);
    int lane = threadIdx.x & 31;
    int sub = lane % L;
    int slot = lane / L;

    for (int u = gw; u < UNITS; u += NWARP) {
        int node = u * NPW + slot;
        float2 acc = __half22float2(__ldg(&hp[(size_t)node * L + sub]));  // self loop
        int e = __ldg(&g_rowptr[node]);
        int rem = __ldg(&g_deg[node]);
        for (; rem >= 8; rem -= 8, e += 8) {
            int s[8];
#pragma unroll
            for (int j = 0; j < 8; j++) s[j] = __ldg(g_csr + e + j);
            __half2 v[8];
#pragma unroll
            for (int j = 0; j < 8; j++) v[j] = __ldg(&hp[(size_t)s[j] * L + sub]);
            float sx = 0.f, sy = 0.f;
#pragma unroll
            for (int j = 0; j < 8; j++) {
                float2 f = __half22float2(v[j]);
                sx += f.x; sy += f.y;
            }
            acc.x += sx; acc.y += sy;
        }
        for (; rem >= 2; rem -= 2, e += 2) {
            int s0 = __ldg(g_csr + e), s1 = __ldg(g_csr + e + 1);
            float2 v0 = __half22float2(__ldg(&hp[(size_t)s0 * L + sub]));
            float2 v1 = __half22float2(__ldg(&hp[(size_t)s1 * L + sub]));
            acc.x += v0.x + v1.x; acc.y += v0.y + v1.y;
        }
        if (rem) {
            int s = __ldg(g_csr + e);
            float2 v = __half22float2(__ldg(&hp[(size_t)s * L + sub]));
            acc.x += v.x; acc.y += v.y;
        }
        float dv = __ldg(&g_dinv[node]);
        acc.x *= dv; acc.y *= dv;

        float r0 = sbs[4 * sub], r1 = sbs[4 * sub + 1];
        float r2 = sbs[4 * sub + 2], r3 = sbs[4 * sub + 3];
#pragma unroll
        for (int k2 = 0; k2 < L; k2++) {
            float hx = __shfl_sync(0xffffffffu, acc.x, k2, L);
            float hy = __shfl_sync(0xffffffffu, acc.y, k2, L);
            float4 wa = *reinterpret_cast<const float4*>(&sWs[(2 * k2) * FOUT + 4 * sub]);
            float4 wb = *reinterpret_cast<const float4*>(&sWs[(2 * k2 + 1) * FOUT + 4 * sub]);
            r0 += hx * wa.x + hy * wb.x;
            r1 += hx * wa.y + hy * wb.y;
            r2 += hx * wa.z + hy * wb.z;
            r3 += hx * wa.w + hy * wb.w;
        }
        r0 = (r0 >= 0.f) ? r0 : a * r0;
        r1 = (r1 >= 0.f) ? r1 : a * r1;
        r2 = (r2 >= 0.f) ? r2 : a * r2;
        r3 = (r3 >= 0.f) ? r3 : a * r3;

        if (ZOUT) {
            float4 w0 = *reinterpret_cast<const float4*>(&sWfs[(4 * sub + 0) * 4]);
            float4 w1 = *reinterpret_cast<const float4*>(&sWfs[(4 * sub + 1) * 4]);
            float4 w2 = *reinterpret_cast<const float4*>(&sWfs[(4 * sub + 2) * 4]);
            float4 w3 = *reinterpret_cast<const float4*>(&sWfs[(4 * sub + 3) * 4]);
            float pz0 = dv * (r0 * w0.x + r1 * w1.x + r2 * w2.x + r3 * w3.x);
            float pz1 = dv * (r0 * w0.y + r1 * w1.y + r2 * w2.y + r3 * w3.y);
            float pz2 = dv * (r0 * w0.z + r1 * w1.z + r2 * w2.z + r3 * w3.z);
            float pz3 = dv * (r0 * w0.w + r1 * w1.w + r2 * w2.w + r3 * w3.w);
#pragma unroll
            for (int off = 1; off < 16; off <<= 1) {
                pz0 += __shfl_xor_sync(0xffffffffu, pz0, off);
                pz1 += __shfl_xor_sync(0xffffffffu, pz1, off);
                pz2 += __shfl_xor_sync(0xffffffffu, pz2, off);
                pz3 += __shfl_xor_sync(0xffffffffu, pz3, off);
            }
            if (sub == 0) g_z[node] = make_float4(pz0, pz1, pz2, pz3);
        } else {
            __half2 o0 = __floats2half2_rn(r0 * dv, r1 * dv);
            __half2 o1 = __floats2half2_rn(r2 * dv, r3 * dv);
            uint2 pk = make_uint2(h2u(o0), h2u(o1));
            reinterpret_cast<uint2*>(hpo)[(size_t)node * L + sub] = pk;
        }
    }
}

// ---------------- the whole pipeline in one persistent kernel ----------------
__global__ void __launch_bounds__(BLK, 4)
mega(const float* __restrict__ x, const int* __restrict__ es,
     const int* __restrict__ ed, const int* __restrict__ bt,
     const float* __restrict__ W1, const float* __restrict__ b1,
     const float* __restrict__ W2, const float* __restrict__ b2,
     const float* __restrict__ W3, const float* __restrict__ b3,
     const float* __restrict__ W4, const float* __restrict__ b4,
     const float* __restrict__ a1, const float* __restrict__ a2,
     const float* __restrict__ a3,
     const float* __restrict__ Wlin, const float* __restrict__ blin,
     float* __restrict__ out)
{
    __shared__ float sWs[2048];
    __shared__ float sbs[64];
    __shared__ float sWfs[256];

    int tid = threadIdx.x;
    int gtid = blockIdx.x * BLK + tid;

    // phase 0: zero accumulators
    for (int i = gtid; i < NN; i += GSTRIDE) g_deg[i] = 0;
    if (gtid < GG * 4) g_psum[gtid] = 0.f;
    if (gtid < GG) g_pcnt[gtid] = 0;
    gsync();

    // phase 1: degree count (+ block 0 folds head weights Wf = W4 @ Wlin)
    for (int e = gtid; e < EE; e += GSTRIDE) atomicAdd(&g_deg[__ldg(&ed[e])], 1);
    if (blockIdx.x == 0) {
        int o = tid >> 2, c = tid & 3;
        float acc = 0.f;
#pragma unroll 16
        for (int j = 0; j < 128; j++)
            acc += __ldg(&W4[o * 128 + j]) * __ldg(&Wlin[j * 4 + c]);
        g_Wf[tid] = acc;
        if (tid < 4) {
            float bb = __ldg(&blin[tid]);
            for (int j = 0; j < 128; j++) bb += __ldg(&b4[j]) * __ldg(&Wlin[j * 4 + tid]);
            g_bf[tid] = bb;
        }
    }
    gsync();

    // phase 2: dinv + graph counts + prescaled fp16 layer-1 features
    for (int n = gtid; n < NN; n += GSTRIDE) {
        float d = rsqrtf((float)(g_deg[n] + 1));
        g_dinv[n] = d;
        int b = __ldg(&bt[n]);
        g_db[n] = make_float2(d, __int_as_float(b));
        atomicAdd(&g_pcnt[b], 1);
        float4 v0 = reinterpret_cast<const float4*>(x)[n * 2];
        float4 v1 = reinterpret_cast<const float4*>(x)[n * 2 + 1];
        __half2 h0 = __floats2half2_rn(v0.x * d, v0.y * d);
        __half2 h1 = __floats2half2_rn(v0.z * d, v0.w * d);
        __half2 h2 = __floats2half2_rn(v1.x * d, v1.y * d);
        __half2 h3 = __floats2half2_rn(v1.z * d, v1.w * d);
        reinterpret_cast<uint4*>(g_hp0)[n] =
            make_uint4(h2u(h0), h2u(h1), h2u(h2), h2u(h3));
    }
    gsync();

    // phase 3: block-local exclusive scan of deg (chunk = blockIdx.x)
    if (blockIdx.x < NB) {
        int i = blockIdx.x * 256 + tid;
        int v = (i < NN) ? g_deg[i] : 0;
        int lane = tid & 31, w = tid >> 5;
        int xx = v;
#pragma unroll
        for (int d = 1; d < 32; d <<= 1) {
            int y = __shfl_up_sync(0xffffffffu, xx, d);
            if (lane >= d) xx += y;
        }
        int* ws = (int*)sbs;
        if (lane == 31) ws[w] = xx;
        __syncthreads();
        if (w == 0) {
            int y = (lane < 8) ? ws[lane] : 0;
#pragma unroll
            for (int d = 1; d < 8; d <<= 1) {
                int z = __shfl_up_sync(0xffffffffu, y, d);
                if (lane >= d) y += z;
            }
            if (lane < 8) ws[lane] = y;
        }
        __syncthreads();
        int base = (w > 0) ? ws[w - 1] : 0;
        int incl = base + xx;
        if (i < NN) g_rowptr[i] = incl - v;
        if (tid == 255) g_bsum[blockIdx.x] = incl;
    }
    gsync();

    // phase 4: block 0 exclusive-scans the NB block sums (Hillis-Steele, 512 slots)
    if (blockIdx.x == 0) {
        int* si = (int*)sWs;
        si[tid] = (tid < NB) ? g_bsum[tid] : 0;
        si[tid + 256] = (tid + 256 < NB) ? g_bsum[tid + 256] : 0;
        __syncthreads();
        for (int off = 1; off < 512; off <<= 1) {
            int a0 = (tid >= off) ? si[tid - off] : 0;
            int a1 = (tid + 256 >= off) ? si[tid + 256 - off] : 0;
            __syncthreads();
            si[tid] += a0; si[tid + 256] += a1;
            __syncthreads();
        }
        if (tid < NB) g_bsum[tid] = (tid == 0) ? 0 : si[tid - 1];
        if (tid + 256 < NB) g_bsum[tid + 256] = si[tid + 255];
    }
    gsync();

    // phase 5: finalize rowptr + fill cursor
    for (int i = gtid; i < NN; i += GSTRIDE) {
        int r = g_rowptr[i] + g_bsum[i >> 8];
        g_rowptr[i] = r;
        g_cnt[i] = r;
    }
    gsync();

    // phase 6: fill CSR
    for (int e = gtid; e < EE; e += GSTRIDE) {
        int d = __ldg(&ed[e]);
        int pos = atomicAdd(&g_cnt[d], 1);
        g_csr[pos] = __ldg(&es[e]);
    }
    gsync();

    // layers 1-3 (layer 3 emits z = hp3 @ Wf directly)
    layer_phase<8, 16, false>(g_hp0, g_hp1, W1, b1, a1, sWs, sbs, sWfs);
    gsync();
    layer_phase<16, 32, false>(g_hp1, g_hp2, W2, b2, a2, sWs, sbs, sWfs);
    gsync();
    layer_phase<32, 64, true>(g_hp2, nullptr, W3, b3, a3, sWs, sbs, sWfs);
    gsync();

    // layer 4 + mean-pool numerator: edge-parallel over z
    {
        float* acc = sWs;
        acc[tid] = 0.f;
        __syncthreads();
        const long long T = (long long)EE + NN;
        for (long long t = gtid; t < T; t += GSTRIDE) {
            int s, d;
            if (t < EE) { s = __ldg(&es[t]); d = __ldg(&ed[t]); }
            else        { s = d = (int)(t - EE); }
            float2 db = __ldg(&g_db[d]);
            float w = db.x;
            int g = __float_as_int(db.y);
            float4 z = __ldg(&g_z[s]);
            atomicAdd(&acc[g * 4 + 0], w * z.x);
            atomicAdd(&acc[g * 4 + 1], w * z.y);
            atomicAdd(&acc[g * 4 + 2], w * z.z);
            atomicAdd(&acc[g * 4 + 3], w * z.w);
        }
        __syncthreads();
        float v = acc[tid];
        if (v != 0.f) atomicAdd(&g_psum[tid], v);
    }
    gsync();

    // head
    if (blockIdx.x == 0) {
        int g = tid >> 2, cls = tid & 3;
        float inv = 1.f / fmaxf((float)g_pcnt[g], 1.f);
        out[tid] = g_psum[g * 4 + cls] * inv + g_bf[cls];
    }
}

// ---------------- launch ----------------
extern "C" void kernel_launch(void* const* d_in, const int* in_sizes, int n_in,
                              void* d_out, int out_size) {
    const float* x    = (const float*)d_in[0];
    const int*   es   = (const int*)d_in[1];
    const int*   ed   = (const int*)d_in[2];
    const int*   bt   = (const int*)d_in[3];
    const float* W1   = (const float*)d_in[4];
    const float* b1   = (const float*)d_in[5];
    const float* W2   = (const float*)d_in[6];
    const float* b2   = (const float*)d_in[7];
    const float* W3   = (const float*)d_in[8];
    const float* b3   = (const float*)d_in[9];
    const float* W4   = (const float*)d_in[10];
    const float* b4   = (const float*)d_in[11];
    const float* a1   = (const float*)d_in[12];
    const float* a2   = (const float*)d_in[13];
    const float* a3   = (const float*)d_in[14];
    const float* Wlin = (const float*)d_in[15];
    const float* blin = (const float*)d_in[16];

    mega<<<GRID, BLK>>>(x, es, ed, bt, W1, b1, W2, b2, W3, b3, W4, b4,
                        a1, a2, a3, Wlin, blin, (float*)d_out);
}

// round 10
// speedup vs baseline: 1.4763x; 1.4763x over previous
#include <cuda_runtime.h>
#include <cuda_fp16.h>

#define NN 100000
#define EE 1600000
#define GG 64
#define NB ((NN + 255) / 256)   // 391 scan blocks

// ---------------- device scratch ----------------
__device__ alignas(16) __half2 g_hp0[NN * 4];    // 8 feats as 4 half2
__device__ alignas(16) __half2 g_hp1[NN * 8];    // 16 feats
__device__ alignas(16) __half2 g_hp2[NN * 16];   // 32 feats
__device__ float4 g_z[NN];          // per-node z = hp3 @ Wf (layer-3 epilogue)
__device__ int   g_csr[EE];
__device__ int   g_rowptr[NN];
__device__ int   g_cnt[NN];
__device__ int   g_deg[NN];         // in-degree WITHOUT self loop
__device__ float g_dinv[NN];
__device__ float2 g_db[NN];         // {dinv, bitcast(batch)}
__device__ int   g_bsum[NB];
__device__ float g_psum[GG * 4];
__device__ int   g_pcnt[GG];
__device__ float g_Wf[64 * 4];      // W4 @ Wlin
__device__ float g_bf[4];           // b4 @ Wlin + blin

__device__ __forceinline__ unsigned h2u(__half2 h) {
    return *reinterpret_cast<unsigned*>(&h);
}

// ---------------- init / degree ----------------
__global__ void k_zero() {
    int i = blockIdx.x * blockDim.x + threadIdx.x;
    if (i < NN) g_deg[i] = 0;
    if (i < GG * 4) g_psum[i] = 0.0f;
    if (i < GG) g_pcnt[i] = 0;
}
__global__ void k_deg_count(const int* __restrict__ dst) {
    int e = blockIdx.x * blockDim.x + threadIdx.x;
    if (e < EE) atomicAdd(&g_deg[dst[e]], 1);
}
// dinv + graph counts + prescaled fp16 layer-1 features + fused head weights
__global__ void k_dinv_prep(const int* __restrict__ batch, const float* __restrict__ x,
                            const float* __restrict__ W4, const float* __restrict__ b4,
                            const float* __restrict__ Wlin, const float* __restrict__ blin) {
    int n = blockIdx.x * blockDim.x + threadIdx.x;
    if (n < NN) {
        float d = rsqrtf((float)(g_deg[n] + 1));
        g_dinv[n] = d;
        int b = batch[n];
        g_db[n] = make_float2(d, __int_as_float(b));
        atomicAdd(&g_pcnt[b], 1);
        float4 v0 = reinterpret_cast<const float4*>(x)[n * 2];
        float4 v1 = reinterpret_cast<const float4*>(x)[n * 2 + 1];
        __half2 h0 = __floats2half2_rn(v0.x * d, v0.y * d);
        __half2 h1 = __floats2half2_rn(v0.z * d, v0.w * d);
        __half2 h2 = __floats2half2_rn(v1.x * d, v1.y * d);
        __half2 h3 = __floats2half2_rn(v1.z * d, v1.w * d);
        uint4 pk = make_uint4(h2u(h0), h2u(h1), h2u(h2), h2u(h3));
        reinterpret_cast<uint4*>(g_hp0)[n] = pk;
    }
    if (blockIdx.x == 0) {
        int t = threadIdx.x;           // 256 = 64 rows x 4 cols
        int o = t >> 2, c = t & 3;
        float acc = 0.0f;
#pragma unroll 16
        for (int j = 0; j < 128; j++)
            acc += __ldg(&W4[o * 128 + j]) * __ldg(&Wlin[j * 4 + c]);
        g_Wf[o * 4 + c] = acc;
        if (t < 4) {
            float bb = blin[t];
            for (int j = 0; j < 128; j++) bb += b4[j] * __ldg(&Wlin[j * 4 + t]);
            g_bf[t] = bb;
        }
    }
}

// ---------------- scan: block-local exclusive + block sums ----------------
__global__ void k_scan1() {
    int t = threadIdx.x;
    int i = blockIdx.x * 256 + t;
    int v = (i < NN) ? g_deg[i] : 0;
    int lane = t & 31, w = t >> 5;
    int x = v;
#pragma unroll
    for (int d = 1; d < 32; d <<= 1) {
        int y = __shfl_up_sync(0xffffffffu, x, d);
        if (lane >= d) x += y;
    }
    __shared__ int ws[8];
    if (lane == 31) ws[w] = x;
    __syncthreads();
    if (w == 0) {
        int y = (lane < 8) ? ws[lane] : 0;
#pragma unroll
        for (int d = 1; d < 8; d <<= 1) {
            int z = __shfl_up_sync(0xffffffffu, y, d);
            if (lane >= d) y += z;
        }
        if (lane < 8) ws[lane] = y;
    }
    __syncthreads();
    int base = (w > 0) ? ws[w - 1] : 0;
    int incl = base + x;
    if (i < NN) {
        int ex = incl - v;
        g_rowptr[i] = ex;
        g_cnt[i] = ex;
    }
    if (t == 255) g_bsum[blockIdx.x] = incl;
}
__global__ void k_scan2() {
    int t = threadIdx.x;                       // 512 threads
    int v = (t < NB) ? g_bsum[t] : 0;
    int lane = t & 31, w = t >> 5;
    int x = v;
#pragma unroll
    for (int d = 1; d < 32; d <<= 1) {
        int y = __shfl_up_sync(0xffffffffu, x, d);
        if (lane >= d) x += y;
    }
    __shared__ int ws[16];
    if (lane == 31) ws[w] = x;
    __syncthreads();
    if (w == 0) {
        int y = (lane < 16) ? ws[lane] : 0;
#pragma unroll
        for (int d = 1; d < 16; d <<= 1) {
            int z = __shfl_up_sync(0xffffffffu, y, d);
            if (lane >= d) y += z;
        }
        if (lane < 16) ws[lane] = y;
    }
    __syncthreads();
    int base = (w > 0) ? ws[w - 1] : 0;
    if (t < NB) g_bsum[t] = base + x - v;
}
__global__ void k_fill(const int* __restrict__ src, const int* __restrict__ dst) {
    int e = blockIdx.x * blockDim.x + threadIdx.x;
    if (e < EE) {
        int d = dst[e];
        int pos = atomicAdd(&g_cnt[d], 1) + __ldg(&g_bsum[d >> 8]);
        g_csr[pos] = src[e];
    }
}

// ---------------- fused layers 1-3 (fp16 feats, pipelined index prefetch) ------
__device__ __forceinline__ const __half2* hp_in_of(int layer) {
    switch (layer) { case 1: return g_hp0; case 2: return g_hp1;
                     default: return g_hp2; }
}
__device__ __forceinline__ __half2* hp_out_of(int layer) {
    switch (layer) { case 1: return g_hp1; default: return g_hp2; }
}

template<int LYR, int FIN, int FOUT>
__global__ void __launch_bounds__(256)
k_layer(const float* __restrict__ W, const float* __restrict__ b,
        const float* __restrict__ aP)
{
    constexpr int L = FIN / 2;            // half2 lanes per node
    constexpr int NPW = 32 / L;           // nodes per warp
    constexpr bool ZOUT = (LYR == 3);
    static_assert(FOUT == 4 * L, "mapping assumes FOUT = 2*FIN");
    __shared__ alignas(16) float Ws[FIN * FOUT];
    __shared__ float bs[FOUT];
    __shared__ alignas(16) float Wfs[64 * 4];
    for (int i = threadIdx.x; i < FIN * FOUT; i += blockDim.x) Ws[i] = W[i];
    for (int i = threadIdx.x; i < FOUT; i += blockDim.x) bs[i] = b[i];
    if constexpr (ZOUT)
        for (int i = threadIdx.x; i < 256; i += blockDim.x) Wfs[i] = g_Wf[i];
    __syncthreads();
    float a = __ldg(aP);

    int warp = threadIdx.x >> 5, lane = threadIdx.x & 31;
    int sub = lane % L;
    int node = (blockIdx.x * 8 + warp) * NPW + lane / L;
    if (node >= NN) return;

    const __half2* __restrict__ hp = hp_in_of(LYR);
    float2 acc = __half22float2(__ldg(&hp[(size_t)node * L + sub]));  // self loop
    int e = __ldg(&g_rowptr[node]) + __ldg(&g_bsum[node >> 8]);
    int deg = __ldg(&g_deg[node]);

    // software-pipelined: batch of 4 indices prefetched one stage ahead
    int idx = 0;
    int s[4];
    int nb = deg >> 2;                  // number of full 4-batches
    if (nb > 0) {
#pragma unroll
        for (int j = 0; j < 4; j++) s[j] = __ldg(g_csr + e + j);
    }
    for (int bch = 0; bch < nb; bch++) {
        int cur[4];
#pragma unroll
        for (int j = 0; j < 4; j++) cur[j] = s[j];
        int ebase = e + (bch + 1) * 4;
        if (bch + 1 < nb) {
#pragma unroll
            for (int j = 0; j < 4; j++) s[j] = __ldg(g_csr + ebase + j);
        }
        __half2 v[4];
#pragma unroll
        for (int j = 0; j < 4; j++) v[j] = __ldg(&hp[(size_t)cur[j] * L + sub]);
        float sx = 0.f, sy = 0.f;
#pragma unroll
        for (int j = 0; j < 4; j++) {
            float2 f = __half22float2(v[j]);
            sx += f.x; sy += f.y;
        }
        acc.x += sx; acc.y += sy;
    }
    idx = nb << 2;
    for (; idx < deg; idx++) {
        int ss = __ldg(g_csr + e + idx);
        float2 v = __half22float2(__ldg(&hp[(size_t)ss * L + sub]));
        acc.x += v.x; acc.y += v.y;
    }
    float dv = __ldg(&g_dinv[node]);
    acc.x *= dv; acc.y *= dv;

    float r0 = bs[4 * sub], r1 = bs[4 * sub + 1];
    float r2 = bs[4 * sub + 2], r3 = bs[4 * sub + 3];
#pragma unroll
    for (int k2 = 0; k2 < L; k2++) {
        float hx = __shfl_sync(0xffffffffu, acc.x, k2, L);
        float hy = __shfl_sync(0xffffffffu, acc.y, k2, L);
        float4 wa = *reinterpret_cast<const float4*>(&Ws[(2 * k2) * FOUT + 4 * sub]);
        float4 wb = *reinterpret_cast<const float4*>(&Ws[(2 * k2 + 1) * FOUT + 4 * sub]);
        r0 += hx * wa.x + hy * wb.x;
        r1 += hx * wa.y + hy * wb.y;
        r2 += hx * wa.z + hy * wb.z;
        r3 += hx * wa.w + hy * wb.w;
    }
    r0 = (r0 >= 0.f) ? r0 : a * r0;
    r1 = (r1 >= 0.f) ? r1 : a * r1;
    r2 = (r2 >= 0.f) ? r2 : a * r2;
    r3 = (r3 >= 0.f) ? r3 : a * r3;

    if constexpr (ZOUT) {
        float4 w0 = *reinterpret_cast<const float4*>(&Wfs[(4 * sub + 0) * 4]);
        float4 w1 = *reinterpret_cast<const float4*>(&Wfs[(4 * sub + 1) * 4]);
        float4 w2 = *reinterpret_cast<const float4*>(&Wfs[(4 * sub + 2) * 4]);
        float4 w3 = *reinterpret_cast<const float4*>(&Wfs[(4 * sub + 3) * 4]);
        float pz0 = dv * (r0 * w0.x + r1 * w1.x + r2 * w2.x + r3 * w3.x);
        float pz1 = dv * (r0 * w0.y + r1 * w1.y + r2 * w2.y + r3 * w3.y);
        float pz2 = dv * (r0 * w0.z + r1 * w1.z + r2 * w2.z + r3 * w3.z);
        float pz3 = dv * (r0 * w0.w + r1 * w1.w + r2 * w2.w + r3 * w3.w);
#pragma unroll
        for (int off = 1; off < 16; off <<= 1) {
            pz0 += __shfl_xor_sync(0xffffffffu, pz0, off);
            pz1 += __shfl_xor_sync(0xffffffffu, pz1, off);
            pz2 += __shfl_xor_sync(0xffffffffu, pz2, off);
            pz3 += __shfl_xor_sync(0xffffffffu, pz3, off);
        }
        if (sub == 0) g_z[node] = make_float4(pz0, pz1, pz2, pz3);
    } else {
        __half2* hp_out = hp_out_of(LYR);
        __half2 o0 = __floats2half2_rn(r0 * dv, r1 * dv);
        __half2 o1 = __floats2half2_rn(r2 * dv, r3 * dv);
        uint2 pk = make_uint2(h2u(o0), h2u(o1));
        reinterpret_cast<uint2*>(hp_out)[(size_t)node * L + sub] = pk;
    }
}

// ---------------- pooled layer-4: edge-parallel over z (16 B per edge) ----------
#define PG 1184
__global__ void __launch_bounds__(256)
k_pool4(const int* __restrict__ src, const int* __restrict__ dst)
{
    __shared__ float acc[GG * 4];
    acc[threadIdx.x] = 0.0f;        // blockDim == 256 == GG*4
    __syncthreads();
    const long long T = (long long)EE + NN;
    for (long long t = (long long)blockIdx.x * blockDim.x + threadIdx.x;
         t < T; t += (long long)PG * 256) {
        int s, d;
        if (t < EE) { s = __ldg(src + t); d = __ldg(dst + t); }
        else        { s = d = (int)(t - EE); }
        float2 db = __ldg(&g_db[d]);
        float w = db.x;
        int g = __float_as_int(db.y);
        float4 z = __ldg(&g_z[s]);
        atomicAdd(&acc[g * 4 + 0], w * z.x);
        atomicAdd(&acc[g * 4 + 1], w * z.y);
        atomicAdd(&acc[g * 4 + 2], w * z.z);
        atomicAdd(&acc[g * 4 + 3], w * z.w);
    }
    __syncthreads();
    float v = acc[threadIdx.x];
    if (v != 0.0f) atomicAdd(&g_psum[threadIdx.x], v);
}

// ---------------- head ----------------
__global__ void k_final(float* __restrict__ out) {
    int t = threadIdx.x;            // 64 graphs x 4 classes
    int g = t >> 2;
    int cls = t & 3;
    float inv = 1.0f / fmaxf((float)g_pcnt[g], 1.0f);
    out[g * 4 + cls] = g_psum[g * 4 + cls] * inv + g_bf[cls];
}

// ---------------- launch ----------------
extern "C" void kernel_launch(void* const* d_in, const int* in_sizes, int n_in,
                              void* d_out, int out_size) {
    const float* x    = (const float*)d_in[0];
    const int*   es   = (const int*)d_in[1];
    const int*   ed   = (const int*)d_in[2];
    const int*   bt   = (const int*)d_in[3];
    const float* W1   = (const float*)d_in[4];
    const float* b1   = (const float*)d_in[5];
    const float* W2   = (const float*)d_in[6];
    const float* b2   = (const float*)d_in[7];
    const float* W3   = (const float*)d_in[8];
    const float* b3   = (const float*)d_in[9];
    const float* W4   = (const float*)d_in[10];
    const float* b4   = (const float*)d_in[11];
    const float* a1   = (const float*)d_in[12];
    const float* a2   = (const float*)d_in[13];
    const float* a3   = (const float*)d_in[14];
    const float* Wlin = (const float*)d_in[15];
    const float* blin = (const float*)d_in[16];

    const int B = 256;
    auto gr = [](long long n, int b) { return (unsigned)((n + b - 1) / b); };

    k_zero<<<gr(NN, B), B>>>();
    k_deg_count<<<gr(EE, B), B>>>(ed);
    k_dinv_prep<<<gr(NN, B), B>>>(bt, x, W4, b4, Wlin, blin);
    k_scan1<<<NB, 256>>>();
    k_scan2<<<1, 512>>>();
    k_fill<<<gr(EE, B), B>>>(es, ed);

    // layers 1-3: sub-warp mapping, nodes/block = 8 * (32/L)
    k_layer<1, 8, 16><<<gr(NN, 64), B>>>(W1, b1, a1);
    k_layer<2, 16, 32><<<gr(NN, 32), B>>>(W2, b2, a2);
    k_layer<3, 32, 64><<<gr(NN, 16), B>>>(W3, b3, a3);   // emits z directly

    // layer 4 + mean-pool numerator: edge-parallel on z
    k_pool4<<<PG, 256>>>(es, ed);

    k_final<<<1, 256>>>((float*)d_out);
}

// round 11
// speedup vs baseline: 1.5371x; 1.0412x over previous
#include <cuda_runtime.h>
#include <cuda_fp16.h>

#define NN 100000
#define EE 1600000
#define GG 64
#define NB ((NN + 255) / 256)   // 391 scan blocks

// ---------------- device scratch ----------------
__device__ alignas(16) __half2 g_hp0[NN * 4];    // 8 feats as 4 half2
__device__ alignas(16) __half2 g_hp1[NN * 8];    // 16 feats
__device__ alignas(16) __half2 g_hp2[NN * 16];   // 32 feats
__device__ float4 g_z[NN];          // per-node z = hp3 @ Wf (layer-3 epilogue)
__device__ int   g_csr[EE];
__device__ int   g_rowptr[NN];
__device__ int   g_cnt[NN];
__device__ int   g_deg[NN];         // in-degree WITHOUT self loop
__device__ float g_dinv[NN];
__device__ float2 g_db[NN];         // {dinv, bitcast(batch)}
__device__ int   g_bsum[NB];
__device__ float g_psum[GG * 4];
__device__ int   g_pcnt[GG];
__device__ float g_Wf[64 * 4];      // W4 @ Wlin
__device__ float g_bf[4];           // b4 @ Wlin + blin

__device__ __forceinline__ unsigned h2u(__half2 h) {
    return *reinterpret_cast<unsigned*>(&h);
}

// ---------------- init / degree ----------------
__global__ void k_zero() {
    int i = blockIdx.x * blockDim.x + threadIdx.x;
    if (i < NN) g_deg[i] = 0;
    if (i < GG * 4) g_psum[i] = 0.0f;
    if (i < GG) g_pcnt[i] = 0;
}
// 2 edges per thread (EE is even)
__global__ void k_deg_count(const int* __restrict__ dst) {
    int t = blockIdx.x * blockDim.x + threadIdx.x;
    if (t < EE / 2) {
        int2 d = reinterpret_cast<const int2*>(dst)[t];
        atomicAdd(&g_deg[d.x], 1);
        atomicAdd(&g_deg[d.y], 1);
    }
}
// dinv + graph counts + prescaled fp16 layer-1 features + fused head weights
__global__ void k_dinv_prep(const int* __restrict__ batch, const float* __restrict__ x,
                            const float* __restrict__ W4, const float* __restrict__ b4,
                            const float* __restrict__ Wlin, const float* __restrict__ blin) {
    int n = blockIdx.x * blockDim.x + threadIdx.x;
    if (n < NN) {
        float d = rsqrtf((float)(g_deg[n] + 1));
        g_dinv[n] = d;
        int b = batch[n];
        g_db[n] = make_float2(d, __int_as_float(b));
        atomicAdd(&g_pcnt[b], 1);
        float4 v0 = reinterpret_cast<const float4*>(x)[n * 2];
        float4 v1 = reinterpret_cast<const float4*>(x)[n * 2 + 1];
        __half2 h0 = __floats2half2_rn(v0.x * d, v0.y * d);
        __half2 h1 = __floats2half2_rn(v0.z * d, v0.w * d);
        __half2 h2 = __floats2half2_rn(v1.x * d, v1.y * d);
        __half2 h3 = __floats2half2_rn(v1.z * d, v1.w * d);
        uint4 pk = make_uint4(h2u(h0), h2u(h1), h2u(h2), h2u(h3));
        reinterpret_cast<uint4*>(g_hp0)[n] = pk;
    }
    if (blockIdx.x == 0) {
        int t = threadIdx.x;           // 256 = 64 rows x 4 cols
        int o = t >> 2, c = t & 3;
        float acc = 0.0f;
#pragma unroll 16
        for (int j = 0; j < 128; j++)
            acc += __ldg(&W4[o * 128 + j]) * __ldg(&Wlin[j * 4 + c]);
        g_Wf[o * 4 + c] = acc;
        if (t < 4) {
            float bb = blin[t];
            for (int j = 0; j < 128; j++) bb += b4[j] * __ldg(&Wlin[j * 4 + t]);
            g_bf[t] = bb;
        }
    }
}

// ---------------- scan: block-local exclusive + block sums ----------------
__global__ void k_scan1() {
    int t = threadIdx.x;
    int i = blockIdx.x * 256 + t;
    int v = (i < NN) ? g_deg[i] : 0;
    int lane = t & 31, w = t >> 5;
    int x = v;
#pragma unroll
    for (int d = 1; d < 32; d <<= 1) {
        int y = __shfl_up_sync(0xffffffffu, x, d);
        if (lane >= d) x += y;
    }
    __shared__ int ws[8];
    if (lane == 31) ws[w] = x;
    __syncthreads();
    if (w == 0) {
        int y = (lane < 8) ? ws[lane] : 0;
#pragma unroll
        for (int d = 1; d < 8; d <<= 1) {
            int z = __shfl_up_sync(0xffffffffu, y, d);
            if (lane >= d) y += z;
        }
        if (lane < 8) ws[lane] = y;
    }
    __syncthreads();
    int base = (w > 0) ? ws[w - 1] : 0;
    int incl = base + x;
    if (i < NN) {
        int ex = incl - v;
        g_rowptr[i] = ex;
        g_cnt[i] = ex;
    }
    if (t == 255) g_bsum[blockIdx.x] = incl;
}
__global__ void k_scan2() {
    int t = threadIdx.x;                       // 512 threads
    int v = (t < NB) ? g_bsum[t] : 0;
    int lane = t & 31, w = t >> 5;
    int x = v;
#pragma unroll
    for (int d = 1; d < 32; d <<= 1) {
        int y = __shfl_up_sync(0xffffffffu, x, d);
        if (lane >= d) x += y;
    }
    __shared__ int ws[16];
    if (lane == 31) ws[w] = x;
    __syncthreads();
    if (w == 0) {
        int y = (lane < 16) ? ws[lane] : 0;
#pragma unroll
        for (int d = 1; d < 16; d <<= 1) {
            int z = __shfl_up_sync(0xffffffffu, y, d);
            if (lane >= d) y += z;
        }
        if (lane < 16) ws[lane] = y;
    }
    __syncthreads();
    int base = (w > 0) ? ws[w - 1] : 0;
    if (t < NB) g_bsum[t] = base + x - v;
}
// 2 edges per thread
__global__ void k_fill(const int* __restrict__ src, const int* __restrict__ dst) {
    int t = blockIdx.x * blockDim.x + threadIdx.x;
    if (t < EE / 2) {
        int2 d = reinterpret_cast<const int2*>(dst)[t];
        int2 s = reinterpret_cast<const int2*>(src)[t];
        int p0 = atomicAdd(&g_cnt[d.x], 1) + __ldg(&g_bsum[d.x >> 8]);
        int p1 = atomicAdd(&g_cnt[d.y], 1) + __ldg(&g_bsum[d.y >> 8]);
        g_csr[p0] = s.x;
        g_csr[p1] = s.y;
    }
}

// ---------------- fused layers 1-3 (fp16 features, R7 gather loop) -------------
__device__ __forceinline__ const __half2* hp_in_of(int layer) {
    switch (layer) { case 1: return g_hp0; case 2: return g_hp1;
                     default: return g_hp2; }
}
__device__ __forceinline__ __half2* hp_out_of(int layer) {
    switch (layer) { case 1: return g_hp1; default: return g_hp2; }
}

template<int LYR, int FIN, int FOUT>
__global__ void __launch_bounds__(256)
k_layer(const float* __restrict__ W, const float* __restrict__ b,
        const float* __restrict__ aP)
{
    constexpr int L = FIN / 2;            // half2 lanes per node
    constexpr int NPW = 32 / L;           // nodes per warp
    constexpr bool ZOUT = (LYR == 3);
    static_assert(FOUT == 4 * L, "mapping assumes FOUT = 2*FIN");
    __shared__ alignas(16) float Ws[FIN * FOUT];
    __shared__ float bs[FOUT];
    __shared__ alignas(16) float Wfs[64 * 4];
    for (int i = threadIdx.x; i < FIN * FOUT; i += blockDim.x) Ws[i] = W[i];
    for (int i = threadIdx.x; i < FOUT; i += blockDim.x) bs[i] = b[i];
    if constexpr (ZOUT)
        for (int i = threadIdx.x; i < 256; i += blockDim.x) Wfs[i] = g_Wf[i];
    __syncthreads();
    float a = __ldg(aP);

    int warp = threadIdx.x >> 5, lane = threadIdx.x & 31;
    int sub = lane % L;
    int node = (blockIdx.x * 8 + warp) * NPW + lane / L;
    if (node >= NN) return;

    const __half2* __restrict__ hp = hp_in_of(LYR);
    float2 acc = __half22float2(__ldg(&hp[(size_t)node * L + sub]));  // self loop
    int e = __ldg(&g_rowptr[node]) + __ldg(&g_bsum[node >> 8]);
    int rem = __ldg(&g_deg[node]);
    for (; rem >= 8; rem -= 8, e += 8) {
        int s[8];
#pragma unroll
        for (int j = 0; j < 8; j++) s[j] = __ldg(g_csr + e + j);
        __half2 v[8];
#pragma unroll
        for (int j = 0; j < 8; j++) v[j] = __ldg(&hp[(size_t)s[j] * L + sub]);
        float sx = 0.f, sy = 0.f;
#pragma unroll
        for (int j = 0; j < 8; j++) {
            float2 f = __half22float2(v[j]);
            sx += f.x; sy += f.y;
        }
        acc.x += sx; acc.y += sy;
    }
    for (; rem >= 2; rem -= 2, e += 2) {
        int s0 = __ldg(g_csr + e), s1 = __ldg(g_csr + e + 1);
        float2 v0 = __half22float2(__ldg(&hp[(size_t)s0 * L + sub]));
        float2 v1 = __half22float2(__ldg(&hp[(size_t)s1 * L + sub]));
        acc.x += v0.x + v1.x; acc.y += v0.y + v1.y;
    }
    if (rem) {
        int s = __ldg(g_csr + e);
        float2 v = __half22float2(__ldg(&hp[(size_t)s * L + sub]));
        acc.x += v.x; acc.y += v.y;
    }
    float dv = __ldg(&g_dinv[node]);
    acc.x *= dv; acc.y *= dv;

    float r0 = bs[4 * sub], r1 = bs[4 * sub + 1];
    float r2 = bs[4 * sub + 2], r3 = bs[4 * sub + 3];
#pragma unroll
    for (int k2 = 0; k2 < L; k2++) {
        float hx = __shfl_sync(0xffffffffu, acc.x, k2, L);
        float hy = __shfl_sync(0xffffffffu, acc.y, k2, L);
        float4 wa = *reinterpret_cast<const float4*>(&Ws[(2 * k2) * FOUT + 4 * sub]);
        float4 wb = *reinterpret_cast<const float4*>(&Ws[(2 * k2 + 1) * FOUT + 4 * sub]);
        r0 += hx * wa.x + hy * wb.x;
        r1 += hx * wa.y + hy * wb.y;
        r2 += hx * wa.z + hy * wb.z;
        r3 += hx * wa.w + hy * wb.w;
    }
    r0 = (r0 >= 0.f) ? r0 : a * r0;
    r1 = (r1 >= 0.f) ? r1 : a * r1;
    r2 = (r2 >= 0.f) ? r2 : a * r2;
    r3 = (r3 >= 0.f) ? r3 : a * r3;

    if constexpr (ZOUT) {
        float4 w0 = *reinterpret_cast<const float4*>(&Wfs[(4 * sub + 0) * 4]);
        float4 w1 = *reinterpret_cast<const float4*>(&Wfs[(4 * sub + 1) * 4]);
        float4 w2 = *reinterpret_cast<const float4*>(&Wfs[(4 * sub + 2) * 4]);
        float4 w3 = *reinterpret_cast<const float4*>(&Wfs[(4 * sub + 3) * 4]);
        float pz0 = dv * (r0 * w0.x + r1 * w1.x + r2 * w2.x + r3 * w3.x);
        float pz1 = dv * (r0 * w0.y + r1 * w1.y + r2 * w2.y + r3 * w3.y);
        float pz2 = dv * (r0 * w0.z + r1 * w1.z + r2 * w2.z + r3 * w3.z);
        float pz3 = dv * (r0 * w0.w + r1 * w1.w + r2 * w2.w + r3 * w3.w);
#pragma unroll
        for (int off = 1; off < 16; off <<= 1) {
            pz0 += __shfl_xor_sync(0xffffffffu, pz0, off);
            pz1 += __shfl_xor_sync(0xffffffffu, pz1, off);
            pz2 += __shfl_xor_sync(0xffffffffu, pz2, off);
            pz3 += __shfl_xor_sync(0xffffffffu, pz3, off);
        }
        if (sub == 0) g_z[node] = make_float4(pz0, pz1, pz2, pz3);
    } else {
        __half2* hp_out = hp_out_of(LYR);
        __half2 o0 = __floats2half2_rn(r0 * dv, r1 * dv);
        __half2 o1 = __floats2half2_rn(r2 * dv, r3 * dv);
        uint2 pk = make_uint2(h2u(o0), h2u(o1));
        reinterpret_cast<uint2*>(hp_out)[(size_t)node * L + sub] = pk;
    }
}

// ---------------- pooled layer-4: edge-parallel over z (16 B per edge) ----------
#define PG 1184
__global__ void __launch_bounds__(256)
k_pool4(const int* __restrict__ src, const int* __restrict__ dst)
{
    __shared__ float acc[GG * 4];
    acc[threadIdx.x] = 0.0f;        // blockDim == 256 == GG*4
    __syncthreads();
    const long long T = (long long)EE + NN;
    const long long STR = (long long)PG * 256;
    for (long long t = (long long)blockIdx.x * blockDim.x + threadIdx.x;
         t < T; t += 2 * STR) {
        long long t1 = t + STR;
        int s0, d0, s1 = -1, d1 = -1;
        if (t < EE) { s0 = __ldg(src + t); d0 = __ldg(dst + t); }
        else        { s0 = d0 = (int)(t - EE); }
        bool has1 = (t1 < T);
        if (has1) {
            if (t1 < EE) { s1 = __ldg(src + t1); d1 = __ldg(dst + t1); }
            else         { s1 = d1 = (int)(t1 - EE); }
        }
        float2 db0 = __ldg(&g_db[d0]);
        float4 z0 = __ldg(&g_z[s0]);
        float2 db1 = has1 ? __ldg(&g_db[d1]) : make_float2(0.f, 0.f);
        float4 z1 = has1 ? __ldg(&g_z[s1]) : make_float4(0.f, 0.f, 0.f, 0.f);
        int g0 = __float_as_int(db0.y);
        atomicAdd(&acc[g0 * 4 + 0], db0.x * z0.x);
        atomicAdd(&acc[g0 * 4 + 1], db0.x * z0.y);
        atomicAdd(&acc[g0 * 4 + 2], db0.x * z0.z);
        atomicAdd(&acc[g0 * 4 + 3], db0.x * z0.w);
        if (has1) {
            int g1 = __float_as_int(db1.y);
            atomicAdd(&acc[g1 * 4 + 0], db1.x * z1.x);
            atomicAdd(&acc[g1 * 4 + 1], db1.x * z1.y);
            atomicAdd(&acc[g1 * 4 + 2], db1.x * z1.z);
            atomicAdd(&acc[g1 * 4 + 3], db1.x * z1.w);
        }
    }
    __syncthreads();
    float v = acc[threadIdx.x];
    if (v != 0.0f) atomicAdd(&g_psum[threadIdx.x], v);
}

// ---------------- head ----------------
__global__ void k_final(float* __restrict__ out) {
    int t = threadIdx.x;            // 64 graphs x 4 classes
    int g = t >> 2;
    int cls = t & 3;
    float inv = 1.0f / fmaxf((float)g_pcnt[g], 1.0f);
    out[g * 4 + cls] = g_psum[g * 4 + cls] * inv + g_bf[cls];
}

// ---------------- launch ----------------
extern "C" void kernel_launch(void* const* d_in, const int* in_sizes, int n_in,
                              void* d_out, int out_size) {
    const float* x    = (const float*)d_in[0];
    const int*   es   = (const int*)d_in[1];
    const int*   ed   = (const int*)d_in[2];
    const int*   bt   = (const int*)d_in[3];
    const float* W1   = (const float*)d_in[4];
    const float* b1   = (const float*)d_in[5];
    const float* W2   = (const float*)d_in[6];
    const float* b2   = (const float*)d_in[7];
    const float* W3   = (const float*)d_in[8];
    const float* b3   = (const float*)d_in[9];
    const float* W4   = (const float*)d_in[10];
    const float* b4   = (const float*)d_in[11];
    const float* a1   = (const float*)d_in[12];
    const float* a2   = (const float*)d_in[13];
    const float* a3   = (const float*)d_in[14];
    const float* Wlin = (const float*)d_in[15];
    const float* blin = (const float*)d_in[16];

    const int B = 256;
    auto gr = [](long long n, int b) { return (unsigned)((n + b - 1) / b); };

    k_zero<<<gr(NN, B), B>>>();
    k_deg_count<<<gr(EE / 2, B), B>>>(ed);
    k_dinv_prep<<<gr(NN, B), B>>>(bt, x, W4, b4, Wlin, blin);
    k_scan1<<<NB, 256>>>();
    k_scan2<<<1, 512>>>();
    k_fill<<<gr(EE / 2, B), B>>>(es, ed);

    // layers 1-3: sub-warp mapping, nodes/block = 8 * (32/L)
    k_layer<1, 8, 16><<<gr(NN, 64), B>>>(W1, b1, a1);
    k_layer<2, 16, 32><<<gr(NN, 32), B>>>(W2, b2, a2);
    k_layer<3, 32, 64><<<gr(NN, 16), B>>>(W3, b3, a3);   // emits z directly

    // layer 4 + mean-pool numerator: edge-parallel on z
    k_pool4<<<PG, 256>>>(es, ed);

    k_final<<<1, 256>>>((float*)d_out);
}